// round 14
// baseline (speedup 1.0000x reference)
#include <cuda_runtime.h>
#include <math.h>

// ---------------- static config ----------------
// B=2, C=128, H=W=T=32, OUT=256, WS=4, SHIFT=2, HEADS=8, hd=16, N=64, MLP=512

typedef unsigned long long u64;

// ---------------- device scratch ----------------
__device__ float g_t  [2 * 32768 * 128];     // activations, token-major
__device__ float g_w  [2 * 32768 * 128];     // dw-conv out
__device__ float g_qkv[1024 * 3 * 64 * 128]; // per-window Q,K,V tiles
__device__ float g_h  [1024 * 64 * 512];     // MLP hidden (post-GELU)
__device__ float g_psum[1024 * 256];
__device__ float g_psqr[1024 * 256];
__device__ float g_bnsc[256];
__device__ float g_bnsh[256];

__device__ __forceinline__ int region(int q) { return q < 28 ? 0 : (q < 30 ? 1 : 2); }
__device__ __forceinline__ float gelu_exact(float v) {
    return 0.5f * v * (1.0f + erff(v * 0.70710678118654752f));
}

// ---------------- packed fp32x2 helpers ----------------
__device__ __forceinline__ void ffma2(u64 &d, u64 a, u64 b) {
    asm("fma.rn.f32x2 %0, %1, %2, %0;" : "+l"(d) : "l"(a), "l"(b));
}
__device__ __forceinline__ float2 unpk(u64 v) {
    float2 f; asm("mov.b64 {%0,%1}, %2;" : "=f"(f.x), "=f"(f.y) : "l"(v)); return f;
}
__device__ __forceinline__ float f2sum(u64 v) { float2 f = unpk(v); return f.x + f.y; }
__device__ __forceinline__ u64 fpack(float lo, float hi) {
    u64 r; asm("mov.b64 %0, {%1,%2};" : "=l"(r) : "f"(lo), "f"(hi)); return r;
}

// skewed row offset for attention tiles (16B-aligned skew): row*132 + (row>>4)*4
__device__ __forceinline__ int skew4(int row) { return row * 132 + ((row >> 4) << 2); }

// ---------------- conflict-free weight tile: 64 rows x 128 ch -> u64 pitch 65 ----------------
__device__ __forceinline__ void load_w_tile65(u64* Ws, const float* __restrict__ gw,
                                              int ld, int tid) {
#pragma unroll
    for (int j = 0; j < 8; j++) {
        int i4 = tid + 256 * j;
        int row = i4 >> 5, col = i4 & 31;
        float4 v = ((const float4*)(gw + (size_t)row * ld))[col];
        u64* d = Ws + row * 65 + 2 * col;
        d[0] = ((const u64*)&v)[0];
        d[1] = ((const u64*)&v)[1];
    }
}

// ---------------- register-tiled packed GEMM: 4 tokens x 4 features, 128 channels ----------------
template<int XP>
__device__ __forceinline__ void gemm130(const float* __restrict__ X0,
                                        const u64* __restrict__ W,
                                        int fl, u64 acc[4][4]) {
    const ulonglong2* x0 = (const ulonglong2*)(X0);
    const ulonglong2* x1 = (const ulonglong2*)(X0 + XP);
    const ulonglong2* x2 = (const ulonglong2*)(X0 + 2 * XP);
    const ulonglong2* x3 = (const ulonglong2*)(X0 + 3 * XP);
    const u64* w0 = W + fl * 65;
    const u64* w1 = w0 + 16 * 65;
    const u64* w2 = w0 + 32 * 65;
    const u64* w3 = w0 + 48 * 65;
#pragma unroll 4
    for (int c = 0; c < 32; c++) {
        ulonglong2 Xa = x0[c], Xb = x1[c], Xc = x2[c], Xd = x3[c];
        u64 Wa0 = w0[2*c], Wa1 = w0[2*c+1];
        u64 Wb0 = w1[2*c], Wb1 = w1[2*c+1];
        u64 Wc0 = w2[2*c], Wc1 = w2[2*c+1];
        u64 Wd0 = w3[2*c], Wd1 = w3[2*c+1];
        ffma2(acc[0][0], Xa.x, Wa0); ffma2(acc[0][0], Xa.y, Wa1);
        ffma2(acc[1][0], Xb.x, Wa0); ffma2(acc[1][0], Xb.y, Wa1);
        ffma2(acc[2][0], Xc.x, Wa0); ffma2(acc[2][0], Xc.y, Wa1);
        ffma2(acc[3][0], Xd.x, Wa0); ffma2(acc[3][0], Xd.y, Wa1);
        ffma2(acc[0][1], Xa.x, Wb0); ffma2(acc[0][1], Xa.y, Wb1);
        ffma2(acc[1][1], Xb.x, Wb0); ffma2(acc[1][1], Xb.y, Wb1);
        ffma2(acc[2][1], Xc.x, Wb0); ffma2(acc[2][1], Xc.y, Wb1);
        ffma2(acc[3][1], Xd.x, Wb0); ffma2(acc[3][1], Xd.y, Wb1);
        ffma2(acc[0][2], Xa.x, Wc0); ffma2(acc[0][2], Xa.y, Wc1);
        ffma2(acc[1][2], Xb.x, Wc0); ffma2(acc[1][2], Xb.y, Wc1);
        ffma2(acc[2][2], Xc.x, Wc0); ffma2(acc[2][2], Xc.y, Wc1);
        ffma2(acc[3][2], Xd.x, Wc0); ffma2(acc[3][2], Xd.y, Wc1);
        ffma2(acc[0][3], Xa.x, Wd0); ffma2(acc[0][3], Xa.y, Wd1);
        ffma2(acc[1][3], Xb.x, Wd0); ffma2(acc[1][3], Xb.y, Wd1);
        ffma2(acc[2][3], Xc.x, Wd0); ffma2(acc[2][3], Xc.y, Wd1);
        ffma2(acc[3][3], Xd.x, Wd0); ffma2(acc[3][3], Xd.y, Wd1);
    }
}

// ---------------- input transpose ----------------
__global__ void k_tin(const float* __restrict__ x) {
    __shared__ float tile[32][33];
    int p0  = blockIdx.x * 32;
    int bc0 = blockIdx.y * 32;
    int lx = threadIdx.x, ly = threadIdx.y;
#pragma unroll
    for (int r = 0; r < 32; r += 8)
        tile[ly + r][lx] = x[(size_t)(bc0 + ly + r) * 32768 + p0 + lx];
    __syncthreads();
#pragma unroll
    for (int r = 0; r < 32; r += 8) {
        int p  = p0 + ly + r;
        int bc = bc0 + lx;
        g_t[(size_t)((bc >> 7) * 32768 + p) * 128 + (bc & 127)] = tile[lx][ly + r];
    }
}

// ---------------- QKV GEMM with fused LN1 + shift + partition: g_t -> g_qkv ----------------
__global__ void __launch_bounds__(256, 3) k_qkv(
    const float* __restrict__ qw, const float* __restrict__ qb,
    const float* __restrict__ g1, const float* __restrict__ b1, int shift) {
    extern __shared__ float sm[];
    float* Xs = sm;
    u64*   Wu = (u64*)(sm + 8448);
    int tid = threadIdx.x;
    int widx = blockIdx.x;
    int bb = widx >> 9, wh = (widx >> 6) & 7, ww = (widx >> 3) & 7, wz = widx & 7;

    int warp = tid >> 5, lane = tid & 31;
    float4 gg = ((const float4*)g1)[lane];
    float4 bv = ((const float4*)b1)[lane];
#pragma unroll 1
    for (int pass = 0; pass < 8; pass++) {
        int n = pass * 8 + warp;
        int a = n >> 4, b2 = (n >> 2) & 3, c2 = n & 3;
        int hh = (wh * 4 + a  + shift) & 31;
        int w2 = (ww * 4 + b2 + shift) & 31;
        int t2 = (wz * 4 + c2 + shift) & 31;
        const float4* src = (const float4*)(g_t + ((size_t)bb * 32768 + hh * 1024 + w2 * 32 + t2) * 128);
        float4 v = src[lane];
        float s = v.x + v.y + v.z + v.w;
        float q = v.x * v.x + v.y * v.y + v.z * v.z + v.w * v.w;
#pragma unroll
        for (int o = 16; o; o >>= 1) {
            s += __shfl_xor_sync(0xffffffffu, s, o);
            q += __shfl_xor_sync(0xffffffffu, q, o);
        }
        float mu   = s * (1.0f / 128.0f);
        float rstd = rsqrtf(q * (1.0f / 128.0f) - mu * mu + 1e-5f);
        float4 o4;
        o4.x = (v.x - mu) * rstd * gg.x + bv.x;
        o4.y = (v.y - mu) * rstd * gg.y + bv.y;
        o4.z = (v.z - mu) * rstd * gg.z + bv.z;
        o4.w = (v.w - mu) * rstd * gg.w + bv.w;
        ((float4*)(Xs + n * 132))[lane] = o4;
    }

    int tg = tid >> 4, fl = tid & 15;
    const float* Xrow = Xs + 4 * tg * 132;
#pragma unroll 1
    for (int blk = 0; blk < 6; blk++) {
        load_w_tile65(Wu, qw + blk * 64 * 128, 128, tid);
        __syncthreads();
        u64 acc[4][4] = {};
        gemm130<132>(Xrow, Wu, fl, acc);
        int sel = blk >> 1, fo = (blk & 1) * 64;
        float sc = (sel == 0) ? 0.25f : 1.0f;
        float* dst = g_qkv + ((size_t)(widx * 3 + sel) * 64) * 128;
#pragma unroll
        for (int t = 0; t < 4; t++)
#pragma unroll
            for (int j = 0; j < 4; j++) {
                int f = blk * 64 + fl + 16 * j;
                dst[(4 * tg + t) * 128 + fo + fl + 16 * j] = (f2sum(acc[t][j]) + qb[f]) * sc;
            }
        __syncthreads();
    }
}

// ---------------- fused attention + proj + residual: g_qkv -> g_t ----------------
// smem: Qs/Ks/Vs skew4 tiles (8464 floats each) + Rs (rpb 2744) -> 2 CTAs/SM
// O overwrites Qs in-place (safe: per-warp, post-last-use of Q within each head pair);
// proj W tiles reuse dead Ks/Vs space.
__global__ void __launch_bounds__(256, 2) k_attp(
    const float* __restrict__ rpb,
    const float* __restrict__ pw, const float* __restrict__ pb, int shift) {
    extern __shared__ float sm[];
    float* Qs = sm;
    float* Ks = sm + 8464;
    float* Vs = sm + 16928;
    float* Rs = sm + 25392;      // 2744 floats of rpb
    __shared__ int lbl[64];
    __shared__ int dstb[64];
    int tid = threadIdx.x;
    int widx = blockIdx.x;
    int bb = widx >> 9, wh = (widx >> 6) & 7, ww = (widx >> 3) & 7, wz = widx & 7;

    const float* src = g_qkv + (size_t)widx * 3 * 8192;
#pragma unroll 4
    for (int r = 0; r < 32; r++) {
        int idx = tid + 256 * r;
        int row = idx >> 7, col = idx & 127;
        int so = skew4(row) + col;
        Qs[so] = src[idx];
        Ks[so] = src[8192 + idx];
        Vs[so] = src[16384 + idx];
    }
#pragma unroll
    for (int idx = tid; idx < 2744; idx += 256) Rs[idx] = rpb[idx];
    if (tid < 64) {
        int n = tid;
        int a = n >> 4, b2 = (n >> 2) & 3, c2 = n & 3;
        lbl[n] = region(wh * 4 + a) * 9 + region(ww * 4 + b2) * 3 + region(wz * 4 + c2);
        int hh = (wh * 4 + a + shift) & 31;
        int w2 = (ww * 4 + b2 + shift) & 31;
        int t2 = (wz * 4 + c2 + shift) & 31;
        dstb[n] = ((bb << 15) + hh * 1024 + w2 * 32 + t2) * 128;
    }
    __syncthreads();

    int i  = tid >> 2;
    int aj = tid & 3;
    int jb = aj * 16;
    int ai = i >> 4, bi = (i >> 2) & 3, ci = i & 3;
    int rbase = (ai - aj + 3) * 49 + bi * 7 + ci + 24;
    unsigned mkbits = 0;
    if (shift) {
        int li = lbl[i];
#pragma unroll
        for (int jj = 0; jj < 16; jj++)
            if (lbl[jb + jj] != li) mkbits |= (1u << jj);
    }
    float* Qrow = Qs + skew4(i);
    const float* Kblk = Ks + skew4(jb);
    const float* Vblk = Vs + skew4(jb);

#pragma unroll 1
    for (int hp = 0; hp < 4; hp++) {
        int ho = hp * 32;
        ulonglong2 q[8];
        {
            const ulonglong2* qr = (const ulonglong2*)(Qrow + ho);
#pragma unroll
            for (int d = 0; d < 8; d++) q[d] = qr[d];
        }
        float sv0[16], sv1[16];
        float mx0 = -1e30f, mx1 = -1e30f;
#pragma unroll
        for (int jj = 0; jj < 16; jj++) {
            const ulonglong2* kr = (const ulonglong2*)(Kblk + jj * 132 + ho);
            u64 a0 = 0, a1 = 0;
#pragma unroll
            for (int d = 0; d < 4; d++) {
                ulonglong2 kv = kr[d];
                ffma2(a0, q[d].x, kv.x); ffma2(a0, q[d].y, kv.y);
            }
#pragma unroll
            for (int d = 4; d < 8; d++) {
                ulonglong2 kv = kr[d];
                ffma2(a1, q[d].x, kv.x); ffma2(a1, q[d].y, kv.y);
            }
            int bj = (jj >> 2) & 3, cj = jj & 3;
            float2 rv = *(const float2*)(Rs + (rbase - (bj * 7 + cj)) * 8 + 2 * hp);
            float s0 = f2sum(a0) + rv.x;
            float s1 = f2sum(a1) + rv.y;
            if ((mkbits >> jj) & 1) { s0 -= 100.0f; s1 -= 100.0f; }
            sv0[jj] = s0; sv1[jj] = s1;
            mx0 = fmaxf(mx0, s0); mx1 = fmaxf(mx1, s1);
        }
        mx0 = fmaxf(mx0, __shfl_xor_sync(0xffffffffu, mx0, 1));
        mx0 = fmaxf(mx0, __shfl_xor_sync(0xffffffffu, mx0, 2));
        mx1 = fmaxf(mx1, __shfl_xor_sync(0xffffffffu, mx1, 1));
        mx1 = fmaxf(mx1, __shfl_xor_sync(0xffffffffu, mx1, 2));
        float sum0 = 0.0f, sum1 = 0.0f;
#pragma unroll
        for (int jj = 0; jj < 16; jj++) {
            sv0[jj] = __expf(sv0[jj] - mx0); sum0 += sv0[jj];
            sv1[jj] = __expf(sv1[jj] - mx1); sum1 += sv1[jj];
        }
        sum0 += __shfl_xor_sync(0xffffffffu, sum0, 1);
        sum0 += __shfl_xor_sync(0xffffffffu, sum0, 2);
        sum1 += __shfl_xor_sync(0xffffffffu, sum1, 1);
        sum1 += __shfl_xor_sync(0xffffffffu, sum1, 2);
        float inv0 = 1.0f / sum0, inv1 = 1.0f / sum1;

        u64 o0[8] = {}, o1[8] = {};
#pragma unroll
        for (int jj = 0; jj < 16; jj++) {
            const ulonglong2* vr = (const ulonglong2*)(Vblk + jj * 132 + ho);
            u64 s0p = fpack(sv0[jj], sv0[jj]);
            u64 s1p = fpack(sv1[jj], sv1[jj]);
#pragma unroll
            for (int d = 0; d < 4; d++) {
                ulonglong2 vv = vr[d];
                ffma2(o0[2*d],   s0p, vv.x);
                ffma2(o0[2*d+1], s0p, vv.y);
            }
#pragma unroll
            for (int d = 0; d < 4; d++) {
                ulonglong2 vv = vr[d + 4];
                ffma2(o1[2*d],   s1p, vv.x);
                ffma2(o1[2*d+1], s1p, vv.y);
            }
        }
        // O overwrites Q slice for this head pair (last use of q[] was above)
#pragma unroll
        for (int d = 0; d < 4; d++) {
            float2 fa = unpk(o0[2*d]), fb = unpk(o0[2*d+1]);
            fa.x += __shfl_xor_sync(0xffffffffu, fa.x, 1);
            fa.x += __shfl_xor_sync(0xffffffffu, fa.x, 2);
            fa.y += __shfl_xor_sync(0xffffffffu, fa.y, 1);
            fa.y += __shfl_xor_sync(0xffffffffu, fa.y, 2);
            fb.x += __shfl_xor_sync(0xffffffffu, fb.x, 1);
            fb.x += __shfl_xor_sync(0xffffffffu, fb.x, 2);
            fb.y += __shfl_xor_sync(0xffffffffu, fb.y, 1);
            fb.y += __shfl_xor_sync(0xffffffffu, fb.y, 2);
            if (aj == 0)
                ((float4*)(Qrow + ho))[d] =
                    make_float4(fa.x * inv0, fa.y * inv0, fb.x * inv0, fb.y * inv0);
        }
#pragma unroll
        for (int d = 0; d < 4; d++) {
            float2 fa = unpk(o1[2*d]), fb = unpk(o1[2*d+1]);
            fa.x += __shfl_xor_sync(0xffffffffu, fa.x, 1);
            fa.x += __shfl_xor_sync(0xffffffffu, fa.x, 2);
            fa.y += __shfl_xor_sync(0xffffffffu, fa.y, 1);
            fa.y += __shfl_xor_sync(0xffffffffu, fa.y, 2);
            fb.x += __shfl_xor_sync(0xffffffffu, fb.x, 1);
            fb.x += __shfl_xor_sync(0xffffffffu, fb.x, 2);
            fb.y += __shfl_xor_sync(0xffffffffu, fb.y, 1);
            fb.y += __shfl_xor_sync(0xffffffffu, fb.y, 2);
            if (aj == 0)
                ((float4*)(Qrow + ho + 16))[d] =
                    make_float4(fa.x * inv1, fa.y * inv1, fb.x * inv1, fb.y * inv1);
        }
    }

    // ---- proj + residual scatter, O read from Qs; W tiles in dead Ks/Vs space ----
    __syncthreads();
    u64* W0 = (u64*)Ks;
    u64* W1 = (u64*)Vs;
    load_w_tile65(W0, pw, 128, tid);
    load_w_tile65(W1, pw + 64 * 128, 128, tid);
    __syncthreads();
    int tg = tid >> 4, fl = tid & 15;
    const float* Xrow = Qs + skew4(4 * tg);   // rows 4tg..4tg+3 share skew
    {
        u64 acc[4][4] = {};
        gemm130<132>(Xrow, W0, fl, acc);
#pragma unroll
        for (int t = 0; t < 4; t++)
#pragma unroll
            for (int j = 0; j < 4; j++) {
                int f = fl + 16 * j;
                g_t[dstb[4 * tg + t] + f] += f2sum(acc[t][j]) + pb[f];
            }
    }
    {
        u64 acc[4][4] = {};
        gemm130<132>(Xrow, W1, fl, acc);
#pragma unroll
        for (int t = 0; t < 4; t++)
#pragma unroll
            for (int j = 0; j < 4; j++) {
                int f = 64 + fl + 16 * j;
                g_t[dstb[4 * tg + t] + f] += f2sum(acc[t][j]) + pb[f];
            }
    }
}

// ---------------- fc1: LN2 + fc1 + GELU -> g_h ----------------
__global__ void __launch_bounds__(256, 3) k_fc1(
    const float* __restrict__ g2, const float* __restrict__ b2,
    const float* __restrict__ f1w, const float* __restrict__ f1b) {
    extern __shared__ float sm[];
    float* Xs = sm;
    u64*   Wu = (u64*)(sm + 8448);
    int tid = threadIdx.x;
    const float* base = g_t + (size_t)blockIdx.x * 8192;
#pragma unroll 4
    for (int r = 0; r < 32; r++) {
        int idx = tid + 256 * r;
        Xs[(idx >> 7) * 132 + (idx & 127)] = base[idx];
    }
    __syncthreads();
    {
        int i = tid >> 2, l = tid & 3;
        float s = 0.0f, q = 0.0f;
#pragma unroll
        for (int c = l * 32; c < l * 32 + 32; c++) { float v = Xs[i * 132 + c]; s += v; q += v * v; }
        s += __shfl_xor_sync(0xffffffffu, s, 1); s += __shfl_xor_sync(0xffffffffu, s, 2);
        q += __shfl_xor_sync(0xffffffffu, q, 1); q += __shfl_xor_sync(0xffffffffu, q, 2);
        float mu   = s * (1.0f / 128.0f);
        float rstd = rsqrtf(q * (1.0f / 128.0f) - mu * mu + 1e-5f);
#pragma unroll
        for (int c = l * 32; c < l * 32 + 32; c++) {
            float v = Xs[i * 132 + c];
            Xs[i * 132 + c] = (v - mu) * rstd * g2[c] + b2[c];
        }
    }
    __syncthreads();
    int tg = tid >> 4, fl = tid & 15;
    const float* Xrow = Xs + 4 * tg * 132;
    float* hdst = g_h + (size_t)blockIdx.x * 64 * 512;
#pragma unroll 1
    for (int blk = 0; blk < 8; blk++) {
        load_w_tile65(Wu, f1w + blk * 64 * 128, 128, tid);
        __syncthreads();
        u64 acc[4][4] = {};
        gemm130<132>(Xrow, Wu, fl, acc);
#pragma unroll
        for (int t = 0; t < 4; t++)
#pragma unroll
            for (int j = 0; j < 4; j++) {
                int f = blk * 64 + fl + 16 * j;
                hdst[(4 * tg + t) * 512 + f] = gelu_exact(f2sum(acc[t][j]) + f1b[f]);
            }
        __syncthreads();
    }
}

// ---------------- fc2 + residual: g_h -> g_t ----------------
__global__ void __launch_bounds__(256, 3) k_fc2(
    const float* __restrict__ f2w, const float* __restrict__ f2b) {
    extern __shared__ float sm[];
    float* Hs = sm;
    u64*   Wu = (u64*)(sm + 8448);
    int tid = threadIdx.x;
    int tg = tid >> 4, fl = tid & 15;
    float* base = g_t + (size_t)blockIdx.x * 8192;
    const float* hsrc = g_h + (size_t)blockIdx.x * 64 * 512;
    const float* Hrow = Hs + 4 * tg * 132;
#pragma unroll 1
    for (int fblk = 0; fblk < 2; fblk++) {
        u64 acc[4][4] = {};
#pragma unroll 1
        for (int cblk = 0; cblk < 4; cblk++) {
#pragma unroll
            for (int j = 0; j < 8; j++) {
                int i4 = tid + 256 * j;
                int row = i4 >> 5, col = i4 & 31;
                ((float4*)(Hs + row * 132))[col] =
                    ((const float4*)(hsrc + (size_t)row * 512 + cblk * 128))[col];
            }
            load_w_tile65(Wu, f2w + (size_t)(fblk * 64) * 512 + cblk * 128, 512, tid);
            __syncthreads();
            gemm130<132>(Hrow, Wu, fl, acc);
            __syncthreads();
        }
#pragma unroll
        for (int t = 0; t < 4; t++)
#pragma unroll
            for (int j = 0; j < 4; j++) {
                int f = fblk * 64 + fl + 16 * j;
                base[(4 * tg + t) * 128 + f] += f2sum(acc[t][j]) + f2b[f];
            }
    }
}

// ---------------- depthwise 3x3x3 conv: g_t -> g_w (t-sliding window) ----------------
__global__ void k_dw(const float* __restrict__ w, const float* __restrict__ bias) {
    __shared__ float ws[128 * 27];
    int tid = threadIdx.x;
    for (int idx = tid; idx < 128 * 27; idx += 128) ws[idx] = w[idx];
    __syncthreads();
    int c = tid;
    float bv = bias[c];
    int rid = blockIdx.x;
    int bb = rid >> 10, hh = (rid >> 5) & 31, ww = rid & 31;
    const float* base = g_t + (size_t)bb * 32768 * 128;
    float* out = g_w + ((size_t)bb * 32768 + hh * 1024 + ww * 32) * 128;

    float wreg[9][3];
#pragma unroll
    for (int k = 0; k < 9; k++)
#pragma unroll
        for (int dt = 0; dt < 3; dt++)
            wreg[k][dt] = ws[c * 27 + k * 3 + dt];

    int off[9]; bool val[9];
#pragma unroll
    for (int k = 0; k < 9; k++) {
        int dh = k / 3 - 1, dw_ = k % 3 - 1;
        int h2 = hh + dh, w2 = ww + dw_;
        bool v = ((unsigned)h2 < 32u) && ((unsigned)w2 < 32u);
        val[k] = v;
        off[k] = v ? (h2 * 1024 + w2 * 32) * 128 + c : 0;
    }
    float pa[9], pb[9], pc[9];
#pragma unroll
    for (int k = 0; k < 9; k++) {
        pa[k] = 0.0f;
        pb[k] = val[k] ? base[off[k]] : 0.0f;
        pc[k] = val[k] ? base[off[k] + 128] : 0.0f;
    }
#pragma unroll 4
    for (int tt = 0; tt < 32; tt++) {
        float acc = bv;
#pragma unroll
        for (int k = 0; k < 9; k++) {
            acc = fmaf(pa[k], wreg[k][0], acc);
            acc = fmaf(pb[k], wreg[k][1], acc);
            acc = fmaf(pc[k], wreg[k][2], acc);
        }
        out[tt * 128 + c] = acc;
        int tn = tt + 2;
        bool tv = tn < 32;
#pragma unroll
        for (int k = 0; k < 9; k++) {
            pa[k] = pb[k];
            pb[k] = pc[k];
            pc[k] = (tv && val[k]) ? base[off[k] + tn * 128] : 0.0f;
        }
    }
}

// ---------------- pointwise conv 128->256 GEMM + BN partials ----------------
__global__ void __launch_bounds__(256) k_pw(
    const float* __restrict__ w, const float* __restrict__ bias,
    float* __restrict__ out) {
    extern __shared__ float sm[];
    float* Xs = sm;                  // 64 x 132
    float* Zs = sm + 8448;           // 64 x 261
    u64*   Wu = (u64*)(sm + 25152);  // 64 x 65 u64
    int tid = threadIdx.x;
    const float* base = g_w + (size_t)blockIdx.x * 8192;
#pragma unroll 4
    for (int r = 0; r < 32; r++) {
        int idx = tid + 256 * r;
        Xs[(idx >> 7) * 132 + (idx & 127)] = base[idx];
    }
    __syncthreads();
    int tg = tid >> 4, fl = tid & 15;
    const float* Xrow = Xs + 4 * tg * 132;
#pragma unroll 1
    for (int blk = 0; blk < 4; blk++) {
        load_w_tile65(Wu, w + blk * 64 * 128, 128, tid);
        __syncthreads();
        u64 acc[4][4] = {};
        gemm130<132>(Xrow, Wu, fl, acc);
#pragma unroll
        for (int t = 0; t < 4; t++)
#pragma unroll
            for (int j = 0; j < 4; j++) {
                int f = blk * 64 + fl + 16 * j;
                Zs[(4 * tg + t) * 261 + f] = f2sum(acc[t][j]) + bias[f];
            }
        __syncthreads();
    }
    {
        int warp = tid >> 5, lane = tid & 31;
        int token0 = blockIdx.x * 64;
        int bb = token0 >> 15, p0 = token0 & 32767;
        for (int o = warp; o < 256; o += 8) {
            float* op = out + (size_t)(bb * 256 + o) * 32768 + p0;
            op[lane]      = Zs[lane * 261 + o];
            op[lane + 32] = Zs[(lane + 32) * 261 + o];
        }
    }
    {
        int o = tid;
        float s1 = 0.0f, s2 = 0.0f;
#pragma unroll 4
        for (int i = 0; i < 64; i++) { float z = Zs[i * 261 + o]; s1 += z; s2 += z * z; }
        g_psum[blockIdx.x * 256 + o] = s1;
        g_psqr[blockIdx.x * 256 + o] = s2;
    }
}

// ---------------- BN stats reduce (parallel, deterministic tree) ----------------
__global__ void k_bnred(const float* __restrict__ bng, const float* __restrict__ bnb) {
    __shared__ float a1[256], a2[256];
    int o = blockIdx.x, t = threadIdx.x;
    float s1 = 0.0f, s2 = 0.0f;
#pragma unroll 4
    for (int j = t; j < 1024; j += 256) {
        s1 += g_psum[j * 256 + o];
        s2 += g_psqr[j * 256 + o];
    }
    a1[t] = s1; a2[t] = s2;
    __syncthreads();
#pragma unroll
    for (int st = 128; st; st >>= 1) {
        if (t < st) { a1[t] += a1[t + st]; a2[t] += a2[t + st]; }
        __syncthreads();
    }
    if (t == 0) {
        float mu  = a1[0] * (1.0f / 65536.0f);
        float var = a2[0] * (1.0f / 65536.0f) - mu * mu;
        float sc  = bng[o] * rsqrtf(var + 1e-5f);
        g_bnsc[o] = sc;
        g_bnsh[o] = bnb[o] - mu * sc;
    }
}

// ---------------- BN apply + ReLU ----------------
__global__ void k_bnap(float* __restrict__ out) {
    int idx4 = blockIdx.x * 256 + threadIdx.x;
    int o = ((idx4 * 4) >> 15) & 255;
    float sc = g_bnsc[o], sh = g_bnsh[o];
    float4 v = ((float4*)out)[idx4];
    v.x = fmaxf(v.x * sc + sh, 0.0f);
    v.y = fmaxf(v.y * sc + sh, 0.0f);
    v.z = fmaxf(v.z * sc + sh, 0.0f);
    v.w = fmaxf(v.w * sc + sh, 0.0f);
    ((float4*)out)[idx4] = v;
}

// ---------------- host launch ----------------
extern "C" void kernel_launch(void* const* d_in, const int* in_sizes, int n_in,
                              void* d_out, int out_size) {
    const float* x       = (const float*)d_in[0];
    const float* norm1_g = (const float*)d_in[1];
    const float* norm1_b = (const float*)d_in[2];
    const float* qkv_w   = (const float*)d_in[3];
    const float* qkv_b   = (const float*)d_in[4];
    const float* proj_w  = (const float*)d_in[5];
    const float* proj_b  = (const float*)d_in[6];
    const float* rpb     = (const float*)d_in[7];
    const float* norm2_g = (const float*)d_in[8];
    const float* norm2_b = (const float*)d_in[9];
    const float* fc1_w   = (const float*)d_in[10];
    const float* fc1_b   = (const float*)d_in[11];
    const float* fc2_w   = (const float*)d_in[12];
    const float* fc2_b   = (const float*)d_in[13];
    const float* dw_w    = (const float*)d_in[14];
    const float* dw_b    = (const float*)d_in[15];
    const float* pw_w    = (const float*)d_in[16];
    const float* pw_b    = (const float*)d_in[17];
    const float* bn_g    = (const float*)d_in[18];
    const float* bn_b    = (const float*)d_in[19];
    float* out = (float*)d_out;

    const int GSM  = 8448 * 4 + 4160 * 8;          // 67072
    const int ATSM = (3 * 8464 + 2744) * 4;        // 112544
    const int PSM  = 25152 * 4 + 4160 * 8;         // 133888
    cudaFuncSetAttribute(k_qkv,  cudaFuncAttributeMaxDynamicSharedMemorySize, GSM);
    cudaFuncSetAttribute(k_attp, cudaFuncAttributeMaxDynamicSharedMemorySize, ATSM);
    cudaFuncSetAttribute(k_fc1,  cudaFuncAttributeMaxDynamicSharedMemorySize, GSM);
    cudaFuncSetAttribute(k_fc2,  cudaFuncAttributeMaxDynamicSharedMemorySize, GSM);
    cudaFuncSetAttribute(k_pw,   cudaFuncAttributeMaxDynamicSharedMemorySize, PSM);

    k_tin<<<dim3(1024, 8), dim3(32, 8)>>>(x);

    for (int l = 0; l < 4; l++) {
        int shift = (l & 1) ? 2 : 0;
        k_qkv <<<1024, 256, GSM>>>(qkv_w + l * 384 * 128, qkv_b + l * 384,
                                   norm1_g + l * 128, norm1_b + l * 128, shift);
        k_attp<<<1024, 256, ATSM>>>(rpb + l * 343 * 8,
                                    proj_w + l * 128 * 128, proj_b + l * 128, shift);
        k_fc1 <<<1024, 256, GSM>>>(norm2_g + l * 128, norm2_b + l * 128,
                                   fc1_w + l * 512 * 128, fc1_b + l * 512);
        k_fc2 <<<1024, 256, GSM>>>(fc2_w + l * 128 * 512, fc2_b + l * 128);
    }

    k_dw<<<2048, 128>>>(dw_w, dw_b);
    k_pw<<<1024, 256, PSM>>>(pw_w, pw_b, out);
    k_bnred<<<256, 256>>>(bn_g, bn_b);
    k_bnap<<<16384, 256>>>(out);
}

// round 15
// speedup vs baseline: 1.0025x; 1.0025x over previous
#include <cuda_runtime.h>
#include <math.h>

// ---------------- static config ----------------
// B=2, C=128, H=W=T=32, OUT=256, WS=4, SHIFT=2, HEADS=8, hd=16, N=64, MLP=512

typedef unsigned long long u64;

// ---------------- device scratch ----------------
__device__ float g_t  [2 * 32768 * 128];     // activations, token-major
__device__ float g_w  [2 * 32768 * 128];     // dw-conv out
__device__ float g_qkv[1024 * 3 * 64 * 128]; // per-window Q,K,V tiles
__device__ float g_h  [1024 * 64 * 512];     // MLP hidden (post-GELU)
__device__ float g_psum[1024 * 256];
__device__ float g_psqr[1024 * 256];
__device__ float g_bnsc[256];
__device__ float g_bnsh[256];

__device__ __forceinline__ int region(int q) { return q < 28 ? 0 : (q < 30 ? 1 : 2); }
__device__ __forceinline__ float gelu_exact(float v) {
    return 0.5f * v * (1.0f + erff(v * 0.70710678118654752f));
}

// ---------------- packed fp32x2 helpers ----------------
__device__ __forceinline__ void ffma2(u64 &d, u64 a, u64 b) {
    asm("fma.rn.f32x2 %0, %1, %2, %0;" : "+l"(d) : "l"(a), "l"(b));
}
__device__ __forceinline__ float2 unpk(u64 v) {
    float2 f; asm("mov.b64 {%0,%1}, %2;" : "=f"(f.x), "=f"(f.y) : "l"(v)); return f;
}
__device__ __forceinline__ float f2sum(u64 v) { float2 f = unpk(v); return f.x + f.y; }
__device__ __forceinline__ u64 fpack(float lo, float hi) {
    u64 r; asm("mov.b64 %0, {%1,%2};" : "=l"(r) : "f"(lo), "f"(hi)); return r;
}

// skewed row offset for attention tiles (16B-aligned skew): row*132 + (row>>4)*4
__device__ __forceinline__ int skew4(int row) { return row * 132 + ((row >> 4) << 2); }

// ---------------- conflict-free weight tile: 64 rows x 128 ch -> u64 pitch 65 ----------------
__device__ __forceinline__ void load_w_tile65(u64* Ws, const float* __restrict__ gw,
                                              int ld, int tid) {
#pragma unroll
    for (int j = 0; j < 8; j++) {
        int i4 = tid + 256 * j;
        int row = i4 >> 5, col = i4 & 31;
        float4 v = ((const float4*)(gw + (size_t)row * ld))[col];
        u64* d = Ws + row * 65 + 2 * col;
        d[0] = ((const u64*)&v)[0];
        d[1] = ((const u64*)&v)[1];
    }
}

// ---------------- register-tiled packed GEMM: 4 tokens x 4 features, 128 channels ----------------
template<int XP>
__device__ __forceinline__ void gemm130(const float* __restrict__ X0,
                                        const u64* __restrict__ W,
                                        int fl, u64 acc[4][4]) {
    const ulonglong2* x0 = (const ulonglong2*)(X0);
    const ulonglong2* x1 = (const ulonglong2*)(X0 + XP);
    const ulonglong2* x2 = (const ulonglong2*)(X0 + 2 * XP);
    const ulonglong2* x3 = (const ulonglong2*)(X0 + 3 * XP);
    const u64* w0 = W + fl * 65;
    const u64* w1 = w0 + 16 * 65;
    const u64* w2 = w0 + 32 * 65;
    const u64* w3 = w0 + 48 * 65;
#pragma unroll 4
    for (int c = 0; c < 32; c++) {
        ulonglong2 Xa = x0[c], Xb = x1[c], Xc = x2[c], Xd = x3[c];
        u64 Wa0 = w0[2*c], Wa1 = w0[2*c+1];
        u64 Wb0 = w1[2*c], Wb1 = w1[2*c+1];
        u64 Wc0 = w2[2*c], Wc1 = w2[2*c+1];
        u64 Wd0 = w3[2*c], Wd1 = w3[2*c+1];
        ffma2(acc[0][0], Xa.x, Wa0); ffma2(acc[0][0], Xa.y, Wa1);
        ffma2(acc[1][0], Xb.x, Wa0); ffma2(acc[1][0], Xb.y, Wa1);
        ffma2(acc[2][0], Xc.x, Wa0); ffma2(acc[2][0], Xc.y, Wa1);
        ffma2(acc[3][0], Xd.x, Wa0); ffma2(acc[3][0], Xd.y, Wa1);
        ffma2(acc[0][1], Xa.x, Wb0); ffma2(acc[0][1], Xa.y, Wb1);
        ffma2(acc[1][1], Xb.x, Wb0); ffma2(acc[1][1], Xb.y, Wb1);
        ffma2(acc[2][1], Xc.x, Wb0); ffma2(acc[2][1], Xc.y, Wb1);
        ffma2(acc[3][1], Xd.x, Wb0); ffma2(acc[3][1], Xd.y, Wb1);
        ffma2(acc[0][2], Xa.x, Wc0); ffma2(acc[0][2], Xa.y, Wc1);
        ffma2(acc[1][2], Xb.x, Wc0); ffma2(acc[1][2], Xb.y, Wc1);
        ffma2(acc[2][2], Xc.x, Wc0); ffma2(acc[2][2], Xc.y, Wc1);
        ffma2(acc[3][2], Xd.x, Wc0); ffma2(acc[3][2], Xd.y, Wc1);
        ffma2(acc[0][3], Xa.x, Wd0); ffma2(acc[0][3], Xa.y, Wd1);
        ffma2(acc[1][3], Xb.x, Wd0); ffma2(acc[1][3], Xb.y, Wd1);
        ffma2(acc[2][3], Xc.x, Wd0); ffma2(acc[2][3], Xc.y, Wd1);
        ffma2(acc[3][3], Xd.x, Wd0); ffma2(acc[3][3], Xd.y, Wd1);
    }
}

// ---------------- input transpose ----------------
__global__ void k_tin(const float* __restrict__ x) {
    __shared__ float tile[32][33];
    int p0  = blockIdx.x * 32;
    int bc0 = blockIdx.y * 32;
    int lx = threadIdx.x, ly = threadIdx.y;
#pragma unroll
    for (int r = 0; r < 32; r += 8)
        tile[ly + r][lx] = x[(size_t)(bc0 + ly + r) * 32768 + p0 + lx];
    __syncthreads();
#pragma unroll
    for (int r = 0; r < 32; r += 8) {
        int p  = p0 + ly + r;
        int bc = bc0 + lx;
        g_t[(size_t)((bc >> 7) * 32768 + p) * 128 + (bc & 127)] = tile[lx][ly + r];
    }
}

// ---------------- QKV GEMM with fused LN1 + shift + partition: g_t -> g_qkv ----------------
__global__ void __launch_bounds__(256, 3) k_qkv(
    const float* __restrict__ qw, const float* __restrict__ qb,
    const float* __restrict__ g1, const float* __restrict__ b1, int shift) {
    extern __shared__ float sm[];
    float* Xs = sm;
    u64*   Wu = (u64*)(sm + 8448);
    int tid = threadIdx.x;
    int widx = blockIdx.x;
    int bb = widx >> 9, wh = (widx >> 6) & 7, ww = (widx >> 3) & 7, wz = widx & 7;

    int warp = tid >> 5, lane = tid & 31;
    float4 gg = ((const float4*)g1)[lane];
    float4 bv = ((const float4*)b1)[lane];
#pragma unroll 1
    for (int pass = 0; pass < 8; pass++) {
        int n = pass * 8 + warp;
        int a = n >> 4, b2 = (n >> 2) & 3, c2 = n & 3;
        int hh = (wh * 4 + a  + shift) & 31;
        int w2 = (ww * 4 + b2 + shift) & 31;
        int t2 = (wz * 4 + c2 + shift) & 31;
        const float4* src = (const float4*)(g_t + ((size_t)bb * 32768 + hh * 1024 + w2 * 32 + t2) * 128);
        float4 v = src[lane];
        float s = v.x + v.y + v.z + v.w;
        float q = v.x * v.x + v.y * v.y + v.z * v.z + v.w * v.w;
#pragma unroll
        for (int o = 16; o; o >>= 1) {
            s += __shfl_xor_sync(0xffffffffu, s, o);
            q += __shfl_xor_sync(0xffffffffu, q, o);
        }
        float mu   = s * (1.0f / 128.0f);
        float rstd = rsqrtf(q * (1.0f / 128.0f) - mu * mu + 1e-5f);
        float4 o4;
        o4.x = (v.x - mu) * rstd * gg.x + bv.x;
        o4.y = (v.y - mu) * rstd * gg.y + bv.y;
        o4.z = (v.z - mu) * rstd * gg.z + bv.z;
        o4.w = (v.w - mu) * rstd * gg.w + bv.w;
        ((float4*)(Xs + n * 132))[lane] = o4;
    }

    int tg = tid >> 4, fl = tid & 15;
    const float* Xrow = Xs + 4 * tg * 132;
#pragma unroll 1
    for (int blk = 0; blk < 6; blk++) {
        load_w_tile65(Wu, qw + blk * 64 * 128, 128, tid);
        __syncthreads();
        u64 acc[4][4] = {};
        gemm130<132>(Xrow, Wu, fl, acc);
        int sel = blk >> 1, fo = (blk & 1) * 64;
        float sc = (sel == 0) ? 0.25f : 1.0f;
        float* dst = g_qkv + ((size_t)(widx * 3 + sel) * 64) * 128;
#pragma unroll
        for (int t = 0; t < 4; t++)
#pragma unroll
            for (int j = 0; j < 4; j++) {
                int f = blk * 64 + fl + 16 * j;
                dst[(4 * tg + t) * 128 + fo + fl + 16 * j] = (f2sum(acc[t][j]) + qb[f]) * sc;
            }
        __syncthreads();
    }
}

// ---------------- fused attention + proj + residual: g_qkv -> g_t ----------------
// smem: Qs/Ks/Vs skew4 tiles (8464 floats each) + Rs (rpb 2744) -> 2 CTAs/SM
// O overwrites Qs in-place (safe: per-warp, post-last-use of Q within each head pair);
// proj W tiles reuse dead Ks/Vs space.
__global__ void __launch_bounds__(256, 2) k_attp(
    const float* __restrict__ rpb,
    const float* __restrict__ pw, const float* __restrict__ pb, int shift) {
    extern __shared__ float sm[];
    float* Qs = sm;
    float* Ks = sm + 8464;
    float* Vs = sm + 16928;
    float* Rs = sm + 25392;      // 2744 floats of rpb
    __shared__ int lbl[64];
    __shared__ int dstb[64];
    int tid = threadIdx.x;
    int widx = blockIdx.x;
    int bb = widx >> 9, wh = (widx >> 6) & 7, ww = (widx >> 3) & 7, wz = widx & 7;

    const float* src = g_qkv + (size_t)widx * 3 * 8192;
#pragma unroll 4
    for (int r = 0; r < 32; r++) {
        int idx = tid + 256 * r;
        int row = idx >> 7, col = idx & 127;
        int so = skew4(row) + col;
        Qs[so] = src[idx];
        Ks[so] = src[8192 + idx];
        Vs[so] = src[16384 + idx];
    }
#pragma unroll
    for (int idx = tid; idx < 2744; idx += 256) Rs[idx] = rpb[idx];
    if (tid < 64) {
        int n = tid;
        int a = n >> 4, b2 = (n >> 2) & 3, c2 = n & 3;
        lbl[n] = region(wh * 4 + a) * 9 + region(ww * 4 + b2) * 3 + region(wz * 4 + c2);
        int hh = (wh * 4 + a + shift) & 31;
        int w2 = (ww * 4 + b2 + shift) & 31;
        int t2 = (wz * 4 + c2 + shift) & 31;
        dstb[n] = ((bb << 15) + hh * 1024 + w2 * 32 + t2) * 128;
    }
    __syncthreads();

    int i  = tid >> 2;
    int aj = tid & 3;
    int jb = aj * 16;
    int ai = i >> 4, bi = (i >> 2) & 3, ci = i & 3;
    int rbase = (ai - aj + 3) * 49 + bi * 7 + ci + 24;
    unsigned mkbits = 0;
    if (shift) {
        int li = lbl[i];
#pragma unroll
        for (int jj = 0; jj < 16; jj++)
            if (lbl[jb + jj] != li) mkbits |= (1u << jj);
    }
    float* Qrow = Qs + skew4(i);
    const float* Kblk = Ks + skew4(jb);
    const float* Vblk = Vs + skew4(jb);

#pragma unroll 1
    for (int hp = 0; hp < 4; hp++) {
        int ho = hp * 32;
        ulonglong2 q[8];
        {
            const ulonglong2* qr = (const ulonglong2*)(Qrow + ho);
#pragma unroll
            for (int d = 0; d < 8; d++) q[d] = qr[d];
        }
        float sv0[16], sv1[16];
        float mx0 = -1e30f, mx1 = -1e30f;
#pragma unroll
        for (int jj = 0; jj < 16; jj++) {
            const ulonglong2* kr = (const ulonglong2*)(Kblk + jj * 132 + ho);
            u64 a0 = 0, a1 = 0;
#pragma unroll
            for (int d = 0; d < 4; d++) {
                ulonglong2 kv = kr[d];
                ffma2(a0, q[d].x, kv.x); ffma2(a0, q[d].y, kv.y);
            }
#pragma unroll
            for (int d = 4; d < 8; d++) {
                ulonglong2 kv = kr[d];
                ffma2(a1, q[d].x, kv.x); ffma2(a1, q[d].y, kv.y);
            }
            int bj = (jj >> 2) & 3, cj = jj & 3;
            float2 rv = *(const float2*)(Rs + (rbase - (bj * 7 + cj)) * 8 + 2 * hp);
            float s0 = f2sum(a0) + rv.x;
            float s1 = f2sum(a1) + rv.y;
            if ((mkbits >> jj) & 1) { s0 -= 100.0f; s1 -= 100.0f; }
            sv0[jj] = s0; sv1[jj] = s1;
            mx0 = fmaxf(mx0, s0); mx1 = fmaxf(mx1, s1);
        }
        mx0 = fmaxf(mx0, __shfl_xor_sync(0xffffffffu, mx0, 1));
        mx0 = fmaxf(mx0, __shfl_xor_sync(0xffffffffu, mx0, 2));
        mx1 = fmaxf(mx1, __shfl_xor_sync(0xffffffffu, mx1, 1));
        mx1 = fmaxf(mx1, __shfl_xor_sync(0xffffffffu, mx1, 2));
        float sum0 = 0.0f, sum1 = 0.0f;
#pragma unroll
        for (int jj = 0; jj < 16; jj++) {
            sv0[jj] = __expf(sv0[jj] - mx0); sum0 += sv0[jj];
            sv1[jj] = __expf(sv1[jj] - mx1); sum1 += sv1[jj];
        }
        sum0 += __shfl_xor_sync(0xffffffffu, sum0, 1);
        sum0 += __shfl_xor_sync(0xffffffffu, sum0, 2);
        sum1 += __shfl_xor_sync(0xffffffffu, sum1, 1);
        sum1 += __shfl_xor_sync(0xffffffffu, sum1, 2);
        float inv0 = 1.0f / sum0, inv1 = 1.0f / sum1;

        u64 o0[8] = {}, o1[8] = {};
#pragma unroll
        for (int jj = 0; jj < 16; jj++) {
            const ulonglong2* vr = (const ulonglong2*)(Vblk + jj * 132 + ho);
            u64 s0p = fpack(sv0[jj], sv0[jj]);
            u64 s1p = fpack(sv1[jj], sv1[jj]);
#pragma unroll
            for (int d = 0; d < 4; d++) {
                ulonglong2 vv = vr[d];
                ffma2(o0[2*d],   s0p, vv.x);
                ffma2(o0[2*d+1], s0p, vv.y);
            }
#pragma unroll
            for (int d = 0; d < 4; d++) {
                ulonglong2 vv = vr[d + 4];
                ffma2(o1[2*d],   s1p, vv.x);
                ffma2(o1[2*d+1], s1p, vv.y);
            }
        }
        // O overwrites Q slice for this head pair (last use of q[] was above)
#pragma unroll
        for (int d = 0; d < 4; d++) {
            float2 fa = unpk(o0[2*d]), fb = unpk(o0[2*d+1]);
            fa.x += __shfl_xor_sync(0xffffffffu, fa.x, 1);
            fa.x += __shfl_xor_sync(0xffffffffu, fa.x, 2);
            fa.y += __shfl_xor_sync(0xffffffffu, fa.y, 1);
            fa.y += __shfl_xor_sync(0xffffffffu, fa.y, 2);
            fb.x += __shfl_xor_sync(0xffffffffu, fb.x, 1);
            fb.x += __shfl_xor_sync(0xffffffffu, fb.x, 2);
            fb.y += __shfl_xor_sync(0xffffffffu, fb.y, 1);
            fb.y += __shfl_xor_sync(0xffffffffu, fb.y, 2);
            if (aj == 0)
                ((float4*)(Qrow + ho))[d] =
                    make_float4(fa.x * inv0, fa.y * inv0, fb.x * inv0, fb.y * inv0);
        }
#pragma unroll
        for (int d = 0; d < 4; d++) {
            float2 fa = unpk(o1[2*d]), fb = unpk(o1[2*d+1]);
            fa.x += __shfl_xor_sync(0xffffffffu, fa.x, 1);
            fa.x += __shfl_xor_sync(0xffffffffu, fa.x, 2);
            fa.y += __shfl_xor_sync(0xffffffffu, fa.y, 1);
            fa.y += __shfl_xor_sync(0xffffffffu, fa.y, 2);
            fb.x += __shfl_xor_sync(0xffffffffu, fb.x, 1);
            fb.x += __shfl_xor_sync(0xffffffffu, fb.x, 2);
            fb.y += __shfl_xor_sync(0xffffffffu, fb.y, 1);
            fb.y += __shfl_xor_sync(0xffffffffu, fb.y, 2);
            if (aj == 0)
                ((float4*)(Qrow + ho + 16))[d] =
                    make_float4(fa.x * inv1, fa.y * inv1, fb.x * inv1, fb.y * inv1);
        }
    }

    // ---- proj + residual scatter, O read from Qs; W tiles in dead Ks/Vs space ----
    __syncthreads();
    u64* W0 = (u64*)Ks;
    u64* W1 = (u64*)Vs;
    load_w_tile65(W0, pw, 128, tid);
    load_w_tile65(W1, pw + 64 * 128, 128, tid);
    __syncthreads();
    int tg = tid >> 4, fl = tid & 15;
    const float* Xrow = Qs + skew4(4 * tg);   // rows 4tg..4tg+3 share skew
    {
        u64 acc[4][4] = {};
        gemm130<132>(Xrow, W0, fl, acc);
#pragma unroll
        for (int t = 0; t < 4; t++)
#pragma unroll
            for (int j = 0; j < 4; j++) {
                int f = fl + 16 * j;
                g_t[dstb[4 * tg + t] + f] += f2sum(acc[t][j]) + pb[f];
            }
    }
    {
        u64 acc[4][4] = {};
        gemm130<132>(Xrow, W1, fl, acc);
#pragma unroll
        for (int t = 0; t < 4; t++)
#pragma unroll
            for (int j = 0; j < 4; j++) {
                int f = 64 + fl + 16 * j;
                g_t[dstb[4 * tg + t] + f] += f2sum(acc[t][j]) + pb[f];
            }
    }
}

// ---------------- fc1: LN2 + fc1 + GELU -> g_h ----------------
__global__ void __launch_bounds__(256, 3) k_fc1(
    const float* __restrict__ g2, const float* __restrict__ b2,
    const float* __restrict__ f1w, const float* __restrict__ f1b) {
    extern __shared__ float sm[];
    float* Xs = sm;
    u64*   Wu = (u64*)(sm + 8448);
    int tid = threadIdx.x;
    const float* base = g_t + (size_t)blockIdx.x * 8192;
#pragma unroll 4
    for (int r = 0; r < 32; r++) {
        int idx = tid + 256 * r;
        Xs[(idx >> 7) * 132 + (idx & 127)] = base[idx];
    }
    __syncthreads();
    {
        int i = tid >> 2, l = tid & 3;
        float s = 0.0f, q = 0.0f;
#pragma unroll
        for (int c = l * 32; c < l * 32 + 32; c++) { float v = Xs[i * 132 + c]; s += v; q += v * v; }
        s += __shfl_xor_sync(0xffffffffu, s, 1); s += __shfl_xor_sync(0xffffffffu, s, 2);
        q += __shfl_xor_sync(0xffffffffu, q, 1); q += __shfl_xor_sync(0xffffffffu, q, 2);
        float mu   = s * (1.0f / 128.0f);
        float rstd = rsqrtf(q * (1.0f / 128.0f) - mu * mu + 1e-5f);
#pragma unroll
        for (int c = l * 32; c < l * 32 + 32; c++) {
            float v = Xs[i * 132 + c];
            Xs[i * 132 + c] = (v - mu) * rstd * g2[c] + b2[c];
        }
    }
    __syncthreads();
    int tg = tid >> 4, fl = tid & 15;
    const float* Xrow = Xs + 4 * tg * 132;
    float* hdst = g_h + (size_t)blockIdx.x * 64 * 512;
#pragma unroll 1
    for (int blk = 0; blk < 8; blk++) {
        load_w_tile65(Wu, f1w + blk * 64 * 128, 128, tid);
        __syncthreads();
        u64 acc[4][4] = {};
        gemm130<132>(Xrow, Wu, fl, acc);
#pragma unroll
        for (int t = 0; t < 4; t++)
#pragma unroll
            for (int j = 0; j < 4; j++) {
                int f = blk * 64 + fl + 16 * j;
                hdst[(4 * tg + t) * 512 + f] = gelu_exact(f2sum(acc[t][j]) + f1b[f]);
            }
        __syncthreads();
    }
}

// ---------------- fc2 + residual: g_h -> g_t ----------------
__global__ void __launch_bounds__(256, 3) k_fc2(
    const float* __restrict__ f2w, const float* __restrict__ f2b) {
    extern __shared__ float sm[];
    float* Hs = sm;
    u64*   Wu = (u64*)(sm + 8448);
    int tid = threadIdx.x;
    int tg = tid >> 4, fl = tid & 15;
    float* base = g_t + (size_t)blockIdx.x * 8192;
    const float* hsrc = g_h + (size_t)blockIdx.x * 64 * 512;
    const float* Hrow = Hs + 4 * tg * 132;
#pragma unroll 1
    for (int fblk = 0; fblk < 2; fblk++) {
        u64 acc[4][4] = {};
#pragma unroll 1
        for (int cblk = 0; cblk < 4; cblk++) {
#pragma unroll
            for (int j = 0; j < 8; j++) {
                int i4 = tid + 256 * j;
                int row = i4 >> 5, col = i4 & 31;
                ((float4*)(Hs + row * 132))[col] =
                    ((const float4*)(hsrc + (size_t)row * 512 + cblk * 128))[col];
            }
            load_w_tile65(Wu, f2w + (size_t)(fblk * 64) * 512 + cblk * 128, 512, tid);
            __syncthreads();
            gemm130<132>(Hrow, Wu, fl, acc);
            __syncthreads();
        }
#pragma unroll
        for (int t = 0; t < 4; t++)
#pragma unroll
            for (int j = 0; j < 4; j++) {
                int f = fblk * 64 + fl + 16 * j;
                base[(4 * tg + t) * 128 + f] += f2sum(acc[t][j]) + f2b[f];
            }
    }
}

// ---------------- depthwise 3x3x3 conv: g_t -> g_w (t-sliding window) ----------------
__global__ void k_dw(const float* __restrict__ w, const float* __restrict__ bias) {
    __shared__ float ws[128 * 27];
    int tid = threadIdx.x;
    for (int idx = tid; idx < 128 * 27; idx += 128) ws[idx] = w[idx];
    __syncthreads();
    int c = tid;
    float bv = bias[c];
    int rid = blockIdx.x;
    int bb = rid >> 10, hh = (rid >> 5) & 31, ww = rid & 31;
    const float* base = g_t + (size_t)bb * 32768 * 128;
    float* out = g_w + ((size_t)bb * 32768 + hh * 1024 + ww * 32) * 128;

    float wreg[9][3];
#pragma unroll
    for (int k = 0; k < 9; k++)
#pragma unroll
        for (int dt = 0; dt < 3; dt++)
            wreg[k][dt] = ws[c * 27 + k * 3 + dt];

    int off[9]; bool val[9];
#pragma unroll
    for (int k = 0; k < 9; k++) {
        int dh = k / 3 - 1, dw_ = k % 3 - 1;
        int h2 = hh + dh, w2 = ww + dw_;
        bool v = ((unsigned)h2 < 32u) && ((unsigned)w2 < 32u);
        val[k] = v;
        off[k] = v ? (h2 * 1024 + w2 * 32) * 128 + c : 0;
    }
    float pa[9], pb[9], pc[9];
#pragma unroll
    for (int k = 0; k < 9; k++) {
        pa[k] = 0.0f;
        pb[k] = val[k] ? base[off[k]] : 0.0f;
        pc[k] = val[k] ? base[off[k] + 128] : 0.0f;
    }
#pragma unroll 4
    for (int tt = 0; tt < 32; tt++) {
        float acc = bv;
#pragma unroll
        for (int k = 0; k < 9; k++) {
            acc = fmaf(pa[k], wreg[k][0], acc);
            acc = fmaf(pb[k], wreg[k][1], acc);
            acc = fmaf(pc[k], wreg[k][2], acc);
        }
        out[tt * 128 + c] = acc;
        int tn = tt + 2;
        bool tv = tn < 32;
#pragma unroll
        for (int k = 0; k < 9; k++) {
            pa[k] = pb[k];
            pb[k] = pc[k];
            pc[k] = (tv && val[k]) ? base[off[k] + tn * 128] : 0.0f;
        }
    }
}

// ---------------- pointwise conv 128->256 GEMM + BN partials ----------------
__global__ void __launch_bounds__(256) k_pw(
    const float* __restrict__ w, const float* __restrict__ bias,
    float* __restrict__ out) {
    extern __shared__ float sm[];
    float* Xs = sm;                  // 64 x 132
    float* Zs = sm + 8448;           // 64 x 261
    u64*   Wu = (u64*)(sm + 25152);  // 64 x 65 u64
    int tid = threadIdx.x;
    const float* base = g_w + (size_t)blockIdx.x * 8192;
#pragma unroll 4
    for (int r = 0; r < 32; r++) {
        int idx = tid + 256 * r;
        Xs[(idx >> 7) * 132 + (idx & 127)] = base[idx];
    }
    __syncthreads();
    int tg = tid >> 4, fl = tid & 15;
    const float* Xrow = Xs + 4 * tg * 132;
#pragma unroll 1
    for (int blk = 0; blk < 4; blk++) {
        load_w_tile65(Wu, w + blk * 64 * 128, 128, tid);
        __syncthreads();
        u64 acc[4][4] = {};
        gemm130<132>(Xrow, Wu, fl, acc);
#pragma unroll
        for (int t = 0; t < 4; t++)
#pragma unroll
            for (int j = 0; j < 4; j++) {
                int f = blk * 64 + fl + 16 * j;
                Zs[(4 * tg + t) * 261 + f] = f2sum(acc[t][j]) + bias[f];
            }
        __syncthreads();
    }
    {
        int warp = tid >> 5, lane = tid & 31;
        int token0 = blockIdx.x * 64;
        int bb = token0 >> 15, p0 = token0 & 32767;
        for (int o = warp; o < 256; o += 8) {
            float* op = out + (size_t)(bb * 256 + o) * 32768 + p0;
            op[lane]      = Zs[lane * 261 + o];
            op[lane + 32] = Zs[(lane + 32) * 261 + o];
        }
    }
    {
        int o = tid;
        float s1 = 0.0f, s2 = 0.0f;
#pragma unroll 4
        for (int i = 0; i < 64; i++) { float z = Zs[i * 261 + o]; s1 += z; s2 += z * z; }
        g_psum[blockIdx.x * 256 + o] = s1;
        g_psqr[blockIdx.x * 256 + o] = s2;
    }
}

// ---------------- BN stats reduce (parallel, deterministic tree) ----------------
__global__ void k_bnred(const float* __restrict__ bng, const float* __restrict__ bnb) {
    __shared__ float a1[256], a2[256];
    int o = blockIdx.x, t = threadIdx.x;
    float s1 = 0.0f, s2 = 0.0f;
#pragma unroll 4
    for (int j = t; j < 1024; j += 256) {
        s1 += g_psum[j * 256 + o];
        s2 += g_psqr[j * 256 + o];
    }
    a1[t] = s1; a2[t] = s2;
    __syncthreads();
#pragma unroll
    for (int st = 128; st; st >>= 1) {
        if (t < st) { a1[t] += a1[t + st]; a2[t] += a2[t + st]; }
        __syncthreads();
    }
    if (t == 0) {
        float mu  = a1[0] * (1.0f / 65536.0f);
        float var = a2[0] * (1.0f / 65536.0f) - mu * mu;
        float sc  = bng[o] * rsqrtf(var + 1e-5f);
        g_bnsc[o] = sc;
        g_bnsh[o] = bnb[o] - mu * sc;
    }
}

// ---------------- BN apply + ReLU ----------------
__global__ void k_bnap(float* __restrict__ out) {
    int idx4 = blockIdx.x * 256 + threadIdx.x;
    int o = ((idx4 * 4) >> 15) & 255;
    float sc = g_bnsc[o], sh = g_bnsh[o];
    float4 v = ((float4*)out)[idx4];
    v.x = fmaxf(v.x * sc + sh, 0.0f);
    v.y = fmaxf(v.y * sc + sh, 0.0f);
    v.z = fmaxf(v.z * sc + sh, 0.0f);
    v.w = fmaxf(v.w * sc + sh, 0.0f);
    ((float4*)out)[idx4] = v;
}

// ---------------- host launch ----------------
extern "C" void kernel_launch(void* const* d_in, const int* in_sizes, int n_in,
                              void* d_out, int out_size) {
    const float* x       = (const float*)d_in[0];
    const float* norm1_g = (const float*)d_in[1];
    const float* norm1_b = (const float*)d_in[2];
    const float* qkv_w   = (const float*)d_in[3];
    const float* qkv_b   = (const float*)d_in[4];
    const float* proj_w  = (const float*)d_in[5];
    const float* proj_b  = (const float*)d_in[6];
    const float* rpb     = (const float*)d_in[7];
    const float* norm2_g = (const float*)d_in[8];
    const float* norm2_b = (const float*)d_in[9];
    const float* fc1_w   = (const float*)d_in[10];
    const float* fc1_b   = (const float*)d_in[11];
    const float* fc2_w   = (const float*)d_in[12];
    const float* fc2_b   = (const float*)d_in[13];
    const float* dw_w    = (const float*)d_in[14];
    const float* dw_b    = (const float*)d_in[15];
    const float* pw_w    = (const float*)d_in[16];
    const float* pw_b    = (const float*)d_in[17];
    const float* bn_g    = (const float*)d_in[18];
    const float* bn_b    = (const float*)d_in[19];
    float* out = (float*)d_out;

    const int GSM  = 8448 * 4 + 4160 * 8;          // 67072
    const int ATSM = (3 * 8464 + 2744) * 4;        // 112544
    const int PSM  = 25152 * 4 + 4160 * 8;         // 133888
    cudaFuncSetAttribute(k_qkv,  cudaFuncAttributeMaxDynamicSharedMemorySize, GSM);
    cudaFuncSetAttribute(k_attp, cudaFuncAttributeMaxDynamicSharedMemorySize, ATSM);
    cudaFuncSetAttribute(k_fc1,  cudaFuncAttributeMaxDynamicSharedMemorySize, GSM);
    cudaFuncSetAttribute(k_fc2,  cudaFuncAttributeMaxDynamicSharedMemorySize, GSM);
    cudaFuncSetAttribute(k_pw,   cudaFuncAttributeMaxDynamicSharedMemorySize, PSM);

    k_tin<<<dim3(1024, 8), dim3(32, 8)>>>(x);

    for (int l = 0; l < 4; l++) {
        int shift = (l & 1) ? 2 : 0;
        k_qkv <<<1024, 256, GSM>>>(qkv_w + l * 384 * 128, qkv_b + l * 384,
                                   norm1_g + l * 128, norm1_b + l * 128, shift);
        k_attp<<<1024, 256, ATSM>>>(rpb + l * 343 * 8,
                                    proj_w + l * 128 * 128, proj_b + l * 128, shift);
        k_fc1 <<<1024, 256, GSM>>>(norm2_g + l * 128, norm2_b + l * 128,
                                   fc1_w + l * 512 * 128, fc1_b + l * 512);
        k_fc2 <<<1024, 256, GSM>>>(fc2_w + l * 128 * 512, fc2_b + l * 128);
    }

    k_dw<<<2048, 128>>>(dw_w, dw_b);
    k_pw<<<1024, 256, PSM>>>(pw_w, pw_b, out);
    k_bnred<<<256, 256>>>(bn_g, bn_b);
    k_bnap<<<16384, 256>>>(out);
}

// round 16
// speedup vs baseline: 1.0077x; 1.0052x over previous
#include <cuda_runtime.h>
#include <math.h>

// ---------------- static config ----------------
// B=2, C=128, H=W=T=32, OUT=256, WS=4, SHIFT=2, HEADS=8, hd=16, N=64, MLP=512

typedef unsigned long long u64;

// ---------------- device scratch ----------------
__device__ float g_t  [2 * 32768 * 128];     // activations, token-major
__device__ float g_w  [2 * 32768 * 128];     // dw-conv out
__device__ float g_qkv[1024 * 3 * 64 * 128]; // per-window Q,K,V tiles
__device__ float g_h  [1024 * 64 * 512];     // MLP hidden (post-GELU)
__device__ float g_psum[1024 * 256];
__device__ float g_psqr[1024 * 256];
__device__ float g_bnsc[256];
__device__ float g_bnsh[256];

__device__ __forceinline__ int region(int q) { return q < 28 ? 0 : (q < 30 ? 1 : 2); }
__device__ __forceinline__ float gelu_exact(float v) {
    return 0.5f * v * (1.0f + erff(v * 0.70710678118654752f));
}

// ---------------- packed fp32x2 helpers ----------------
__device__ __forceinline__ void ffma2(u64 &d, u64 a, u64 b) {
    asm("fma.rn.f32x2 %0, %1, %2, %0;" : "+l"(d) : "l"(a), "l"(b));
}
__device__ __forceinline__ float2 unpk(u64 v) {
    float2 f; asm("mov.b64 {%0,%1}, %2;" : "=f"(f.x), "=f"(f.y) : "l"(v)); return f;
}
__device__ __forceinline__ float f2sum(u64 v) { float2 f = unpk(v); return f.x + f.y; }
__device__ __forceinline__ u64 fpack(float lo, float hi) {
    u64 r; asm("mov.b64 %0, {%1,%2};" : "=l"(r) : "f"(lo), "f"(hi)); return r;
}

// skewed row offset for attention tiles (16B-aligned skew): row*132 + (row>>4)*4
__device__ __forceinline__ int skew4(int row) { return row * 132 + ((row >> 4) << 2); }

// ---------------- channel-major W tile: Wt[c][f], c=0..31 (4-float quads), f=0..63 ----------------
// pitch 65 in 16B units; reads by 16 consecutive f-lanes are fully coalesced LDS.128
__device__ __forceinline__ void load_w_tileT(ulonglong2* Wt, const float* __restrict__ gw,
                                             int ld, int tid) {
#pragma unroll
    for (int j = 0; j < 8; j++) {
        int i4 = tid + 256 * j;
        int row = i4 >> 5, col = i4 & 31;    // row = feature, col = channel quad
        float4 v = ((const float4*)(gw + (size_t)row * ld))[col];
        ulonglong2 p;
        p.x = ((const u64*)&v)[0];
        p.y = ((const u64*)&v)[1];
        Wt[col * 65 + row] = p;
    }
}

// ---------------- register-tiled packed GEMM: 4 tokens x 4 features, 128 channels ----------------
// X rows pitch XP floats (16B aligned); W channel-major ulonglong2 tile, features fl+{0,16,32,48}
template<int XP>
__device__ __forceinline__ void gemm130(const float* __restrict__ X0,
                                        const ulonglong2* __restrict__ Wt,
                                        int fl, u64 acc[4][4]) {
    const ulonglong2* x0 = (const ulonglong2*)(X0);
    const ulonglong2* x1 = (const ulonglong2*)(X0 + XP);
    const ulonglong2* x2 = (const ulonglong2*)(X0 + 2 * XP);
    const ulonglong2* x3 = (const ulonglong2*)(X0 + 3 * XP);
#pragma unroll 4
    for (int c = 0; c < 32; c++) {
        ulonglong2 Xa = x0[c], Xb = x1[c], Xc = x2[c], Xd = x3[c];
        const ulonglong2* Wc = Wt + c * 65;
        ulonglong2 Wa = Wc[fl];
        ulonglong2 Wb = Wc[fl + 16];
        ulonglong2 Wx = Wc[fl + 32];
        ulonglong2 Wd = Wc[fl + 48];
        ffma2(acc[0][0], Xa.x, Wa.x); ffma2(acc[0][0], Xa.y, Wa.y);
        ffma2(acc[1][0], Xb.x, Wa.x); ffma2(acc[1][0], Xb.y, Wa.y);
        ffma2(acc[2][0], Xc.x, Wa.x); ffma2(acc[2][0], Xc.y, Wa.y);
        ffma2(acc[3][0], Xd.x, Wa.x); ffma2(acc[3][0], Xd.y, Wa.y);
        ffma2(acc[0][1], Xa.x, Wb.x); ffma2(acc[0][1], Xa.y, Wb.y);
        ffma2(acc[1][1], Xb.x, Wb.x); ffma2(acc[1][1], Xb.y, Wb.y);
        ffma2(acc[2][1], Xc.x, Wb.x); ffma2(acc[2][1], Xc.y, Wb.y);
        ffma2(acc[3][1], Xd.x, Wb.x); ffma2(acc[3][1], Xd.y, Wb.y);
        ffma2(acc[0][2], Xa.x, Wx.x); ffma2(acc[0][2], Xa.y, Wx.y);
        ffma2(acc[1][2], Xb.x, Wx.x); ffma2(acc[1][2], Xb.y, Wx.y);
        ffma2(acc[2][2], Xc.x, Wx.x); ffma2(acc[2][2], Xc.y, Wx.y);
        ffma2(acc[3][2], Xd.x, Wx.x); ffma2(acc[3][2], Xd.y, Wx.y);
        ffma2(acc[0][3], Xa.x, Wd.x); ffma2(acc[0][3], Xa.y, Wd.y);
        ffma2(acc[1][3], Xb.x, Wd.x); ffma2(acc[1][3], Xb.y, Wd.y);
        ffma2(acc[2][3], Xc.x, Wd.x); ffma2(acc[2][3], Xc.y, Wd.y);
        ffma2(acc[3][3], Xd.x, Wd.x); ffma2(acc[3][3], Xd.y, Wd.y);
    }
}

// ---------------- input transpose ----------------
__global__ void k_tin(const float* __restrict__ x) {
    __shared__ float tile[32][33];
    int p0  = blockIdx.x * 32;
    int bc0 = blockIdx.y * 32;
    int lx = threadIdx.x, ly = threadIdx.y;
#pragma unroll
    for (int r = 0; r < 32; r += 8)
        tile[ly + r][lx] = x[(size_t)(bc0 + ly + r) * 32768 + p0 + lx];
    __syncthreads();
#pragma unroll
    for (int r = 0; r < 32; r += 8) {
        int p  = p0 + ly + r;
        int bc = bc0 + lx;
        g_t[(size_t)((bc >> 7) * 32768 + p) * 128 + (bc & 127)] = tile[lx][ly + r];
    }
}

// ---------------- QKV GEMM with fused LN1 + shift + partition: g_t -> g_qkv ----------------
__global__ void __launch_bounds__(256, 3) k_qkv(
    const float* __restrict__ qw, const float* __restrict__ qb,
    const float* __restrict__ g1, const float* __restrict__ b1, int shift) {
    extern __shared__ float sm[];
    float* Xs = sm;
    ulonglong2* Wt = (ulonglong2*)(sm + 8448);
    int tid = threadIdx.x;
    int widx = blockIdx.x;
    int bb = widx >> 9, wh = (widx >> 6) & 7, ww = (widx >> 3) & 7, wz = widx & 7;

    int warp = tid >> 5, lane = tid & 31;
    float4 gg = ((const float4*)g1)[lane];
    float4 bv = ((const float4*)b1)[lane];
#pragma unroll 1
    for (int pass = 0; pass < 8; pass++) {
        int n = pass * 8 + warp;
        int a = n >> 4, b2 = (n >> 2) & 3, c2 = n & 3;
        int hh = (wh * 4 + a  + shift) & 31;
        int w2 = (ww * 4 + b2 + shift) & 31;
        int t2 = (wz * 4 + c2 + shift) & 31;
        const float4* src = (const float4*)(g_t + ((size_t)bb * 32768 + hh * 1024 + w2 * 32 + t2) * 128);
        float4 v = src[lane];
        float s = v.x + v.y + v.z + v.w;
        float q = v.x * v.x + v.y * v.y + v.z * v.z + v.w * v.w;
#pragma unroll
        for (int o = 16; o; o >>= 1) {
            s += __shfl_xor_sync(0xffffffffu, s, o);
            q += __shfl_xor_sync(0xffffffffu, q, o);
        }
        float mu   = s * (1.0f / 128.0f);
        float rstd = rsqrtf(q * (1.0f / 128.0f) - mu * mu + 1e-5f);
        float4 o4;
        o4.x = (v.x - mu) * rstd * gg.x + bv.x;
        o4.y = (v.y - mu) * rstd * gg.y + bv.y;
        o4.z = (v.z - mu) * rstd * gg.z + bv.z;
        o4.w = (v.w - mu) * rstd * gg.w + bv.w;
        ((float4*)(Xs + n * 132))[lane] = o4;
    }

    int tg = tid >> 4, fl = tid & 15;
    const float* Xrow = Xs + 4 * tg * 132;
#pragma unroll 1
    for (int blk = 0; blk < 6; blk++) {
        load_w_tileT(Wt, qw + blk * 64 * 128, 128, tid);
        __syncthreads();
        u64 acc[4][4] = {};
        gemm130<132>(Xrow, Wt, fl, acc);
        int sel = blk >> 1, fo = (blk & 1) * 64;
        float sc = (sel == 0) ? 0.25f : 1.0f;
        float* dst = g_qkv + ((size_t)(widx * 3 + sel) * 64) * 128;
#pragma unroll
        for (int t = 0; t < 4; t++)
#pragma unroll
            for (int j = 0; j < 4; j++) {
                int f = blk * 64 + fl + 16 * j;
                dst[(4 * tg + t) * 128 + fo + fl + 16 * j] = (f2sum(acc[t][j]) + qb[f]) * sc;
            }
        __syncthreads();
    }
}

// ---------------- fused attention + proj + residual: g_qkv -> g_t ----------------
__global__ void __launch_bounds__(256, 2) k_attp(
    const float* __restrict__ rpb,
    const float* __restrict__ pw, const float* __restrict__ pb, int shift) {
    extern __shared__ float sm[];
    float* Qs = sm;
    float* Ks = sm + 8464;
    float* Vs = sm + 16928;
    float* Rs = sm + 25392;      // 2744 floats of rpb
    __shared__ int lbl[64];
    __shared__ int dstb[64];
    int tid = threadIdx.x;
    int widx = blockIdx.x;
    int bb = widx >> 9, wh = (widx >> 6) & 7, ww = (widx >> 3) & 7, wz = widx & 7;

    const float* src = g_qkv + (size_t)widx * 3 * 8192;
#pragma unroll 4
    for (int r = 0; r < 32; r++) {
        int idx = tid + 256 * r;
        int row = idx >> 7, col = idx & 127;
        int so = skew4(row) + col;
        Qs[so] = src[idx];
        Ks[so] = src[8192 + idx];
        Vs[so] = src[16384 + idx];
    }
#pragma unroll
    for (int idx = tid; idx < 2744; idx += 256) Rs[idx] = rpb[idx];
    if (tid < 64) {
        int n = tid;
        int a = n >> 4, b2 = (n >> 2) & 3, c2 = n & 3;
        lbl[n] = region(wh * 4 + a) * 9 + region(ww * 4 + b2) * 3 + region(wz * 4 + c2);
        int hh = (wh * 4 + a + shift) & 31;
        int w2 = (ww * 4 + b2 + shift) & 31;
        int t2 = (wz * 4 + c2 + shift) & 31;
        dstb[n] = ((bb << 15) + hh * 1024 + w2 * 32 + t2) * 128;
    }
    __syncthreads();

    int i  = tid >> 2;
    int aj = tid & 3;
    int jb = aj * 16;
    int ai = i >> 4, bi = (i >> 2) & 3, ci = i & 3;
    int rbase = (ai - aj + 3) * 49 + bi * 7 + ci + 24;
    unsigned mkbits = 0;
    if (shift) {
        int li = lbl[i];
#pragma unroll
        for (int jj = 0; jj < 16; jj++)
            if (lbl[jb + jj] != li) mkbits |= (1u << jj);
    }
    float* Qrow = Qs + skew4(i);
    const float* Kblk = Ks + skew4(jb);
    const float* Vblk = Vs + skew4(jb);

#pragma unroll 1
    for (int hp = 0; hp < 4; hp++) {
        int ho = hp * 32;
        ulonglong2 q[8];
        {
            const ulonglong2* qr = (const ulonglong2*)(Qrow + ho);
#pragma unroll
            for (int d = 0; d < 8; d++) q[d] = qr[d];
        }
        float sv0[16], sv1[16];
        float mx0 = -1e30f, mx1 = -1e30f;
#pragma unroll
        for (int jj = 0; jj < 16; jj++) {
            const ulonglong2* kr = (const ulonglong2*)(Kblk + jj * 132 + ho);
            u64 a0 = 0, a1 = 0;
#pragma unroll
            for (int d = 0; d < 4; d++) {
                ulonglong2 kv = kr[d];
                ffma2(a0, q[d].x, kv.x); ffma2(a0, q[d].y, kv.y);
            }
#pragma unroll
            for (int d = 4; d < 8; d++) {
                ulonglong2 kv = kr[d];
                ffma2(a1, q[d].x, kv.x); ffma2(a1, q[d].y, kv.y);
            }
            int bj = (jj >> 2) & 3, cj = jj & 3;
            float2 rv = *(const float2*)(Rs + (rbase - (bj * 7 + cj)) * 8 + 2 * hp);
            float s0 = f2sum(a0) + rv.x;
            float s1 = f2sum(a1) + rv.y;
            if ((mkbits >> jj) & 1) { s0 -= 100.0f; s1 -= 100.0f; }
            sv0[jj] = s0; sv1[jj] = s1;
            mx0 = fmaxf(mx0, s0); mx1 = fmaxf(mx1, s1);
        }
        mx0 = fmaxf(mx0, __shfl_xor_sync(0xffffffffu, mx0, 1));
        mx0 = fmaxf(mx0, __shfl_xor_sync(0xffffffffu, mx0, 2));
        mx1 = fmaxf(mx1, __shfl_xor_sync(0xffffffffu, mx1, 1));
        mx1 = fmaxf(mx1, __shfl_xor_sync(0xffffffffu, mx1, 2));
        float sum0 = 0.0f, sum1 = 0.0f;
#pragma unroll
        for (int jj = 0; jj < 16; jj++) {
            sv0[jj] = __expf(sv0[jj] - mx0); sum0 += sv0[jj];
            sv1[jj] = __expf(sv1[jj] - mx1); sum1 += sv1[jj];
        }
        sum0 += __shfl_xor_sync(0xffffffffu, sum0, 1);
        sum0 += __shfl_xor_sync(0xffffffffu, sum0, 2);
        sum1 += __shfl_xor_sync(0xffffffffu, sum1, 1);
        sum1 += __shfl_xor_sync(0xffffffffu, sum1, 2);
        float inv0 = 1.0f / sum0, inv1 = 1.0f / sum1;

        u64 o0[8] = {}, o1[8] = {};
#pragma unroll
        for (int jj = 0; jj < 16; jj++) {
            const ulonglong2* vr = (const ulonglong2*)(Vblk + jj * 132 + ho);
            u64 s0p = fpack(sv0[jj], sv0[jj]);
            u64 s1p = fpack(sv1[jj], sv1[jj]);
#pragma unroll
            for (int d = 0; d < 4; d++) {
                ulonglong2 vv = vr[d];
                ffma2(o0[2*d],   s0p, vv.x);
                ffma2(o0[2*d+1], s0p, vv.y);
            }
#pragma unroll
            for (int d = 0; d < 4; d++) {
                ulonglong2 vv = vr[d + 4];
                ffma2(o1[2*d],   s1p, vv.x);
                ffma2(o1[2*d+1], s1p, vv.y);
            }
        }
        // O overwrites Q slice for this head pair (last use of q[] was above)
#pragma unroll
        for (int d = 0; d < 4; d++) {
            float2 fa = unpk(o0[2*d]), fb = unpk(o0[2*d+1]);
            fa.x += __shfl_xor_sync(0xffffffffu, fa.x, 1);
            fa.x += __shfl_xor_sync(0xffffffffu, fa.x, 2);
            fa.y += __shfl_xor_sync(0xffffffffu, fa.y, 1);
            fa.y += __shfl_xor_sync(0xffffffffu, fa.y, 2);
            fb.x += __shfl_xor_sync(0xffffffffu, fb.x, 1);
            fb.x += __shfl_xor_sync(0xffffffffu, fb.x, 2);
            fb.y += __shfl_xor_sync(0xffffffffu, fb.y, 1);
            fb.y += __shfl_xor_sync(0xffffffffu, fb.y, 2);
            if (aj == 0)
                ((float4*)(Qrow + ho))[d] =
                    make_float4(fa.x * inv0, fa.y * inv0, fb.x * inv0, fb.y * inv0);
        }
#pragma unroll
        for (int d = 0; d < 4; d++) {
            float2 fa = unpk(o1[2*d]), fb = unpk(o1[2*d+1]);
            fa.x += __shfl_xor_sync(0xffffffffu, fa.x, 1);
            fa.x += __shfl_xor_sync(0xffffffffu, fa.x, 2);
            fa.y += __shfl_xor_sync(0xffffffffu, fa.y, 1);
            fa.y += __shfl_xor_sync(0xffffffffu, fa.y, 2);
            fb.x += __shfl_xor_sync(0xffffffffu, fb.x, 1);
            fb.x += __shfl_xor_sync(0xffffffffu, fb.x, 2);
            fb.y += __shfl_xor_sync(0xffffffffu, fb.y, 1);
            fb.y += __shfl_xor_sync(0xffffffffu, fb.y, 2);
            if (aj == 0)
                ((float4*)(Qrow + ho + 16))[d] =
                    make_float4(fa.x * inv1, fa.y * inv1, fb.x * inv1, fb.y * inv1);
        }
    }

    // ---- proj + residual scatter, O read from Qs; W tiles in dead Ks/Vs space ----
    __syncthreads();
    ulonglong2* W0 = (ulonglong2*)Ks;
    ulonglong2* W1 = (ulonglong2*)Vs;
    load_w_tileT(W0, pw, 128, tid);
    load_w_tileT(W1, pw + 64 * 128, 128, tid);
    __syncthreads();
    int tg = tid >> 4, fl = tid & 15;
    const float* Xrow = Qs + skew4(4 * tg);   // rows 4tg..4tg+3 share skew
    {
        u64 acc[4][4] = {};
        gemm130<132>(Xrow, W0, fl, acc);
#pragma unroll
        for (int t = 0; t < 4; t++)
#pragma unroll
            for (int j = 0; j < 4; j++) {
                int f = fl + 16 * j;
                g_t[dstb[4 * tg + t] + f] += f2sum(acc[t][j]) + pb[f];
            }
    }
    {
        u64 acc[4][4] = {};
        gemm130<132>(Xrow, W1, fl, acc);
#pragma unroll
        for (int t = 0; t < 4; t++)
#pragma unroll
            for (int j = 0; j < 4; j++) {
                int f = 64 + fl + 16 * j;
                g_t[dstb[4 * tg + t] + f] += f2sum(acc[t][j]) + pb[f];
            }
    }
}

// ---------------- fc1: LN2 + fc1 + GELU -> g_h ----------------
__global__ void __launch_bounds__(256, 3) k_fc1(
    const float* __restrict__ g2, const float* __restrict__ b2,
    const float* __restrict__ f1w, const float* __restrict__ f1b) {
    extern __shared__ float sm[];
    float* Xs = sm;
    ulonglong2* Wt = (ulonglong2*)(sm + 8448);
    int tid = threadIdx.x;
    const float* base = g_t + (size_t)blockIdx.x * 8192;
#pragma unroll 4
    for (int r = 0; r < 32; r++) {
        int idx = tid + 256 * r;
        Xs[(idx >> 7) * 132 + (idx & 127)] = base[idx];
    }
    __syncthreads();
    {
        int i = tid >> 2, l = tid & 3;
        float s = 0.0f, q = 0.0f;
#pragma unroll
        for (int c = l * 32; c < l * 32 + 32; c++) { float v = Xs[i * 132 + c]; s += v; q += v * v; }
        s += __shfl_xor_sync(0xffffffffu, s, 1); s += __shfl_xor_sync(0xffffffffu, s, 2);
        q += __shfl_xor_sync(0xffffffffu, q, 1); q += __shfl_xor_sync(0xffffffffu, q, 2);
        float mu   = s * (1.0f / 128.0f);
        float rstd = rsqrtf(q * (1.0f / 128.0f) - mu * mu + 1e-5f);
#pragma unroll
        for (int c = l * 32; c < l * 32 + 32; c++) {
            float v = Xs[i * 132 + c];
            Xs[i * 132 + c] = (v - mu) * rstd * g2[c] + b2[c];
        }
    }
    __syncthreads();
    int tg = tid >> 4, fl = tid & 15;
    const float* Xrow = Xs + 4 * tg * 132;
    float* hdst = g_h + (size_t)blockIdx.x * 64 * 512;
#pragma unroll 1
    for (int blk = 0; blk < 8; blk++) {
        load_w_tileT(Wt, f1w + blk * 64 * 128, 128, tid);
        __syncthreads();
        u64 acc[4][4] = {};
        gemm130<132>(Xrow, Wt, fl, acc);
#pragma unroll
        for (int t = 0; t < 4; t++)
#pragma unroll
            for (int j = 0; j < 4; j++) {
                int f = blk * 64 + fl + 16 * j;
                hdst[(4 * tg + t) * 512 + f] = gelu_exact(f2sum(acc[t][j]) + f1b[f]);
            }
        __syncthreads();
    }
}

// ---------------- fc2 + residual: g_h -> g_t ----------------
__global__ void __launch_bounds__(256, 3) k_fc2(
    const float* __restrict__ f2w, const float* __restrict__ f2b) {
    extern __shared__ float sm[];
    float* Hs = sm;
    ulonglong2* Wt = (ulonglong2*)(sm + 8448);
    int tid = threadIdx.x;
    int tg = tid >> 4, fl = tid & 15;
    float* base = g_t + (size_t)blockIdx.x * 8192;
    const float* hsrc = g_h + (size_t)blockIdx.x * 64 * 512;
    const float* Hrow = Hs + 4 * tg * 132;
#pragma unroll 1
    for (int fblk = 0; fblk < 2; fblk++) {
        u64 acc[4][4] = {};
#pragma unroll 1
        for (int cblk = 0; cblk < 4; cblk++) {
#pragma unroll
            for (int j = 0; j < 8; j++) {
                int i4 = tid + 256 * j;
                int row = i4 >> 5, col = i4 & 31;
                ((float4*)(Hs + row * 132))[col] =
                    ((const float4*)(hsrc + (size_t)row * 512 + cblk * 128))[col];
            }
            load_w_tileT(Wt, f2w + (size_t)(fblk * 64) * 512 + cblk * 128, 512, tid);
            __syncthreads();
            gemm130<132>(Hrow, Wt, fl, acc);
            __syncthreads();
        }
#pragma unroll
        for (int t = 0; t < 4; t++)
#pragma unroll
            for (int j = 0; j < 4; j++) {
                int f = fblk * 64 + fl + 16 * j;
                base[(4 * tg + t) * 128 + f] += f2sum(acc[t][j]) + f2b[f];
            }
    }
}

// ---------------- depthwise 3x3x3 conv: g_t -> g_w (t-sliding window) ----------------
__global__ void k_dw(const float* __restrict__ w, const float* __restrict__ bias) {
    __shared__ float ws[128 * 27];
    int tid = threadIdx.x;
    for (int idx = tid; idx < 128 * 27; idx += 128) ws[idx] = w[idx];
    __syncthreads();
    int c = tid;
    float bv = bias[c];
    int rid = blockIdx.x;
    int bb = rid >> 10, hh = (rid >> 5) & 31, ww = rid & 31;
    const float* base = g_t + (size_t)bb * 32768 * 128;
    float* out = g_w + ((size_t)bb * 32768 + hh * 1024 + ww * 32) * 128;

    float wreg[9][3];
#pragma unroll
    for (int k = 0; k < 9; k++)
#pragma unroll
        for (int dt = 0; dt < 3; dt++)
            wreg[k][dt] = ws[c * 27 + k * 3 + dt];

    int off[9]; bool val[9];
#pragma unroll
    for (int k = 0; k < 9; k++) {
        int dh = k / 3 - 1, dw_ = k % 3 - 1;
        int h2 = hh + dh, w2 = ww + dw_;
        bool v = ((unsigned)h2 < 32u) && ((unsigned)w2 < 32u);
        val[k] = v;
        off[k] = v ? (h2 * 1024 + w2 * 32) * 128 + c : 0;
    }
    float pa[9], pb[9], pc[9];
#pragma unroll
    for (int k = 0; k < 9; k++) {
        pa[k] = 0.0f;
        pb[k] = val[k] ? base[off[k]] : 0.0f;
        pc[k] = val[k] ? base[off[k] + 128] : 0.0f;
    }
#pragma unroll 4
    for (int tt = 0; tt < 32; tt++) {
        float acc = bv;
#pragma unroll
        for (int k = 0; k < 9; k++) {
            acc = fmaf(pa[k], wreg[k][0], acc);
            acc = fmaf(pb[k], wreg[k][1], acc);
            acc = fmaf(pc[k], wreg[k][2], acc);
        }
        out[tt * 128 + c] = acc;
        int tn = tt + 2;
        bool tv = tn < 32;
#pragma unroll
        for (int k = 0; k < 9; k++) {
            pa[k] = pb[k];
            pb[k] = pc[k];
            pc[k] = (tv && val[k]) ? base[off[k] + tn * 128] : 0.0f;
        }
    }
}

// ---------------- pointwise conv 128->256 GEMM + BN partials ----------------
__global__ void __launch_bounds__(256) k_pw(
    const float* __restrict__ w, const float* __restrict__ bias,
    float* __restrict__ out) {
    extern __shared__ float sm[];
    float* Xs = sm;                  // 64 x 132
    float* Zs = sm + 8448;           // 64 x 261
    ulonglong2* Wt = (ulonglong2*)(sm + 25152);
    int tid = threadIdx.x;
    const float* base = g_w + (size_t)blockIdx.x * 8192;
#pragma unroll 4
    for (int r = 0; r < 32; r++) {
        int idx = tid + 256 * r;
        Xs[(idx >> 7) * 132 + (idx & 127)] = base[idx];
    }
    __syncthreads();
    int tg = tid >> 4, fl = tid & 15;
    const float* Xrow = Xs + 4 * tg * 132;
#pragma unroll 1
    for (int blk = 0; blk < 4; blk++) {
        load_w_tileT(Wt, w + blk * 64 * 128, 128, tid);
        __syncthreads();
        u64 acc[4][4] = {};
        gemm130<132>(Xrow, Wt, fl, acc);
#pragma unroll
        for (int t = 0; t < 4; t++)
#pragma unroll
            for (int j = 0; j < 4; j++) {
                int f = blk * 64 + fl + 16 * j;
                Zs[(4 * tg + t) * 261 + f] = f2sum(acc[t][j]) + bias[f];
            }
        __syncthreads();
    }
    {
        int warp = tid >> 5, lane = tid & 31;
        int token0 = blockIdx.x * 64;
        int bb = token0 >> 15, p0 = token0 & 32767;
        for (int o = warp; o < 256; o += 8) {
            float* op = out + (size_t)(bb * 256 + o) * 32768 + p0;
            op[lane]      = Zs[lane * 261 + o];
            op[lane + 32] = Zs[(lane + 32) * 261 + o];
        }
    }
    {
        int o = tid;
        float s1 = 0.0f, s2 = 0.0f;
#pragma unroll 4
        for (int i = 0; i < 64; i++) { float z = Zs[i * 261 + o]; s1 += z; s2 += z * z; }
        g_psum[blockIdx.x * 256 + o] = s1;
        g_psqr[blockIdx.x * 256 + o] = s2;
    }
}

// ---------------- BN stats reduce (parallel, deterministic tree) ----------------
__global__ void k_bnred(const float* __restrict__ bng, const float* __restrict__ bnb) {
    __shared__ float a1[256], a2[256];
    int o = blockIdx.x, t = threadIdx.x;
    float s1 = 0.0f, s2 = 0.0f;
#pragma unroll 4
    for (int j = t; j < 1024; j += 256) {
        s1 += g_psum[j * 256 + o];
        s2 += g_psqr[j * 256 + o];
    }
    a1[t] = s1; a2[t] = s2;
    __syncthreads();
#pragma unroll
    for (int st = 128; st; st >>= 1) {
        if (t < st) { a1[t] += a1[t + st]; a2[t] += a2[t + st]; }
        __syncthreads();
    }
    if (t == 0) {
        float mu  = a1[0] * (1.0f / 65536.0f);
        float var = a2[0] * (1.0f / 65536.0f) - mu * mu;
        float sc  = bng[o] * rsqrtf(var + 1e-5f);
        g_bnsc[o] = sc;
        g_bnsh[o] = bnb[o] - mu * sc;
    }
}

// ---------------- BN apply + ReLU ----------------
__global__ void k_bnap(float* __restrict__ out) {
    int idx4 = blockIdx.x * 256 + threadIdx.x;
    int o = ((idx4 * 4) >> 15) & 255;
    float sc = g_bnsc[o], sh = g_bnsh[o];
    float4 v = ((float4*)out)[idx4];
    v.x = fmaxf(v.x * sc + sh, 0.0f);
    v.y = fmaxf(v.y * sc + sh, 0.0f);
    v.z = fmaxf(v.z * sc + sh, 0.0f);
    v.w = fmaxf(v.w * sc + sh, 0.0f);
    ((float4*)out)[idx4] = v;
}

// ---------------- host launch ----------------
extern "C" void kernel_launch(void* const* d_in, const int* in_sizes, int n_in,
                              void* d_out, int out_size) {
    const float* x       = (const float*)d_in[0];
    const float* norm1_g = (const float*)d_in[1];
    const float* norm1_b = (const float*)d_in[2];
    const float* qkv_w   = (const float*)d_in[3];
    const float* qkv_b   = (const float*)d_in[4];
    const float* proj_w  = (const float*)d_in[5];
    const float* proj_b  = (const float*)d_in[6];
    const float* rpb     = (const float*)d_in[7];
    const float* norm2_g = (const float*)d_in[8];
    const float* norm2_b = (const float*)d_in[9];
    const float* fc1_w   = (const float*)d_in[10];
    const float* fc1_b   = (const float*)d_in[11];
    const float* fc2_w   = (const float*)d_in[12];
    const float* fc2_b   = (const float*)d_in[13];
    const float* dw_w    = (const float*)d_in[14];
    const float* dw_b    = (const float*)d_in[15];
    const float* pw_w    = (const float*)d_in[16];
    const float* pw_b    = (const float*)d_in[17];
    const float* bn_g    = (const float*)d_in[18];
    const float* bn_b    = (const float*)d_in[19];
    float* out = (float*)d_out;

    const int GSM  = 8448 * 4 + 2080 * 16;         // 33792 + 33280 = 67072
    const int ATSM = (3 * 8464 + 2744) * 4;        // 112544
    const int PSM  = 25152 * 4 + 2080 * 16;        // 100608 + 33280 = 133888
    cudaFuncSetAttribute(k_qkv,  cudaFuncAttributeMaxDynamicSharedMemorySize, GSM);
    cudaFuncSetAttribute(k_attp, cudaFuncAttributeMaxDynamicSharedMemorySize, ATSM);
    cudaFuncSetAttribute(k_fc1,  cudaFuncAttributeMaxDynamicSharedMemorySize, GSM);
    cudaFuncSetAttribute(k_fc2,  cudaFuncAttributeMaxDynamicSharedMemorySize, GSM);
    cudaFuncSetAttribute(k_pw,   cudaFuncAttributeMaxDynamicSharedMemorySize, PSM);

    k_tin<<<dim3(1024, 8), dim3(32, 8)>>>(x);

    for (int l = 0; l < 4; l++) {
        int shift = (l & 1) ? 2 : 0;
        k_qkv <<<1024, 256, GSM>>>(qkv_w + l * 384 * 128, qkv_b + l * 384,
                                   norm1_g + l * 128, norm1_b + l * 128, shift);
        k_attp<<<1024, 256, ATSM>>>(rpb + l * 343 * 8,
                                    proj_w + l * 128 * 128, proj_b + l * 128, shift);
        k_fc1 <<<1024, 256, GSM>>>(norm2_g + l * 128, norm2_b + l * 128,
                                   fc1_w + l * 512 * 128, fc1_b + l * 512);
        k_fc2 <<<1024, 256, GSM>>>(fc2_w + l * 128 * 512, fc2_b + l * 128);
    }

    k_dw<<<2048, 128>>>(dw_w, dw_b);
    k_pw<<<1024, 256, PSM>>>(pw_w, pw_b, out);
    k_bnred<<<256, 256>>>(bn_g, bn_b);
    k_bnap<<<16384, 256>>>(out);
}